// round 2
// baseline (speedup 1.0000x reference)
#include <cuda_runtime.h>
#include <math.h>

// Problem constants
#define B_SZ 2
#define T_SEQ 2048
#define E_DIM 2048
#define NHEAD 16
#define NOPE 64
#define ROPE 32
#define VD 64
#define KVR 256
#define QKD 96          // NOPE + ROPE
#define DLAT 288        // KVR + ROPE (latent dim for scores)
#define ROWS 4096       // B*T

// ---------------- scratch (device globals: allocation-free) ----------------
__device__ float g_kvall[ROWS * 288];
__device__ float g_kvnorm[ROWS * 256];
__device__ float g_q[ROWS * 1536];
__device__ float g_qlat[ROWS * NHEAD * DLAT];    // per (b,t,h): [0:256]=q_abs, [256:288]=roped q_pe
__device__ float g_klat[ROWS * DLAT];            // per (b,t):   [0:256]=kv_t,  [256:288]=roped k_pe
__device__ float g_c2[T_SEQ * 64];
__device__ float g_p2[ROWS * 64];
__device__ float g_x[ROWS * NHEAD * 256];
__device__ float g_xv[ROWS * 1024];

// ---------------- generic tiled SGEMM (optional batch, bias, B-transpose) ----------------
template<int BM,int BN,int BK,int TM,int TN,bool TRB>
__global__ void sgemm_kernel(int M,int N,int K,
    const float* __restrict__ A,int lda,long long sA,
    const float* __restrict__ B,int ldb,long long sB,
    float* __restrict__ C,int ldc,long long sC,
    const float* __restrict__ bias)
{
    constexpr int THREADS=(BM/TM)*(BN/TN);
    __shared__ float As[BK][BM+1];
    __shared__ float Bs[BK][BN+1];
    A += (long long)blockIdx.z * sA;
    B += (long long)blockIdx.z * sB;
    C += (long long)blockIdx.z * sC;
    const int bm = blockIdx.y*BM, bn = blockIdx.x*BN;
    const int tid = threadIdx.x;
    const int tcol = tid % (BN/TN), trow = tid / (BN/TN);
    float acc[TM][TN];
    #pragma unroll
    for (int i=0;i<TM;i++)
        #pragma unroll
        for (int j=0;j<TN;j++) acc[i][j]=0.f;

    for (int k0=0;k0<K;k0+=BK) {
        for (int idx=tid; idx<BM*BK; idx+=THREADS) {
            int m = idx / BK, kk = idx - m*BK;
            int gm = bm+m, gk = k0+kk;
            As[kk][m] = (gm<M && gk<K) ? A[(long long)gm*lda+gk] : 0.f;
        }
        for (int idx=tid; idx<BK*BN; idx+=THREADS) {
            int kk = idx / BN, n = idx - kk*BN;
            int gk = k0+kk, gn = bn+n;
            float v = 0.f;
            if (gk<K && gn<N) v = TRB ? B[(long long)gn*ldb+gk] : B[(long long)gk*ldb+gn];
            Bs[kk][n] = v;
        }
        __syncthreads();
        #pragma unroll
        for (int kk=0;kk<BK;kk++) {
            float ra[TM], rb[TN];
            #pragma unroll
            for (int i=0;i<TM;i++) ra[i] = As[kk][trow*TM+i];
            #pragma unroll
            for (int j=0;j<TN;j++) rb[j] = Bs[kk][tcol*TN+j];
            #pragma unroll
            for (int i=0;i<TM;i++)
                #pragma unroll
                for (int j=0;j<TN;j++) acc[i][j] += ra[i]*rb[j];
        }
        __syncthreads();
    }
    #pragma unroll
    for (int i=0;i<TM;i++) {
        int gm = bm + trow*TM + i;
        if (gm >= M) continue;
        #pragma unroll
        for (int j=0;j<TN;j++) {
            int gn = bn + tcol*TN + j;
            if (gn < N) {
                float v = acc[i][j];
                if (bias) v += bias[gn];
                C[(long long)gm*ldc+gn] = v;
            }
        }
    }
}

// ---------------- kv post: layernorm(kv) + rope(k_pe) ----------------
__global__ void kv_post_kernel(const float* __restrict__ kvall,
                               const float* __restrict__ gamma,
                               const float* __restrict__ beta,
                               const int* __restrict__ position,
                               float* __restrict__ kvnorm,
                               float* __restrict__ klat)
{
    int row = blockIdx.x;
    int tid = threadIdx.x;   // 256 threads
    __shared__ float red[256];
    float v = kvall[(size_t)row*288 + tid];
    red[tid] = v;
    __syncthreads();
    for (int s=128;s>0;s>>=1){ if (tid<s) red[tid]+=red[tid+s]; __syncthreads(); }
    float mean = red[0] * (1.f/256.f);
    __syncthreads();
    float d = v - mean;
    red[tid] = d*d;
    __syncthreads();
    for (int s=128;s>0;s>>=1){ if (tid<s) red[tid]+=red[tid+s]; __syncthreads(); }
    float var = red[0] * (1.f/256.f);
    float rstd = rsqrtf(var + 1e-5f);
    kvnorm[(size_t)row*256 + tid] = d*rstd*gamma[tid] + beta[tid];

    if (tid < 16) {
        int t = row & (T_SEQ-1);
        float pos = (float)position[t];
        float freq = expf(-(float)(2*tid) * (9.2103403719761836f/32.f));
        float a = pos * freq;
        float c = cosf(a), s = sinf(a);
        float x0 = kvall[(size_t)row*288 + 256 + 2*tid];
        float x1 = kvall[(size_t)row*288 + 257 + 2*tid];
        klat[(size_t)row*288 + 256 + 2*tid] = x0*c - x1*s;
        klat[(size_t)row*288 + 257 + 2*tid] = x0*s + x1*c;
    }
}

// ---------------- rope for q_pe, write into qlat[...,256:288] ----------------
__global__ void q_rope_kernel(const float* __restrict__ q,
                              const int* __restrict__ position,
                              float* __restrict__ qlat)
{
    int row = blockIdx.x;
    int tid = threadIdx.x;          // 256 = 16 heads * 16 pairs
    int h = tid >> 4, i = tid & 15;
    int t = row & (T_SEQ-1);
    float pos = (float)position[t];
    float freq = expf(-(float)(2*i) * (9.2103403719761836f/32.f));
    float a = pos * freq;
    float c = cosf(a), s = sinf(a);
    const float* qr = q + (size_t)row*1536 + h*96 + 64;
    float x0 = qr[2*i], x1 = qr[2*i+1];
    float* o = qlat + ((size_t)row*NHEAD + h)*DLAT + 256;
    o[2*i]   = x0*c - x1*s;
    o[2*i+1] = x0*s + x1*c;
}

// ---------------- C2 = sinusoid_pe @ fc_c_w + b (rows repeated by 2) ----------------
__global__ void c2_kernel(const float* __restrict__ w,
                          const float* __restrict__ bias,
                          float* __restrict__ c2)
{
    __shared__ float pe[256];
    int p = blockIdx.x;           // 0..1023
    int tid = threadIdx.x;        // 256
    int i = tid >> 1;
    float freq = expf(-(float)(2*i) * (9.2103403719761836f/256.f));
    float a = (float)p * freq;
    pe[tid] = (tid & 1) ? cosf(a) : sinf(a);
    __syncthreads();
    if (tid < 64) {
        float acc = bias[tid];
        for (int k=0;k<256;k++) acc += pe[k]*w[k*64+tid];
        c2[(size_t)(2*p)*64 + tid]   = acc;
        c2[(size_t)(2*p+1)*64 + tid] = acc;
    }
}

// ---------------- kv_t: sparse gated combine, write klat[...,0:256] ----------------
__global__ void kvt_kernel(const float* __restrict__ c2,
                           const float* __restrict__ p2,
                           const float* __restrict__ kvnorm,
                           float* __restrict__ klat)
{
    int row = blockIdx.x;
    int tid = threadIdx.x;  // 128
    int t = row & (T_SEQ-1);
    __shared__ float r1[64], r2[64];
    if (tid < 64) {
        float a = c2[(size_t)t*64 + tid];
        r1[tid] = a * p2[(size_t)row*64 + tid];
        r2[tid] = (t & 1) ? a * p2[(size_t)(row-1)*64 + tid] : 0.f;
    }
    __syncthreads();
    for (int s=32;s>0;s>>=1){ if (tid<s){ r1[tid]+=r1[tid+s]; r2[tid]+=r2[tid+s]; } __syncthreads(); }
    float wself = 1.f/(1.f+expf(-r1[0]));
    float wprev = (t & 1) ? 1.f/(1.f+expf(-r2[0])) : 0.f;
    for (int c=tid; c<256; c+=128) {
        float v = wself * kvnorm[(size_t)row*256 + c];
        if (t & 1) v += wprev * kvnorm[(size_t)(row-1)*256 + c];
        klat[(size_t)row*288 + c] = v;
    }
}

// ---------------- flash attention over odd keys + self term ----------------
// Grid: (T/32, H, B). Block 256: thread = (tq = tid>>3 in [0,32), c8 = tid&7).
// Each thread owns output dims {c8 + 8*m : m in [0,32)}.
#define FQS 289     // padded row stride (odd -> conflict-free)
#define FLASH_SMEM ((2*32*FQS + 32*33) * 4)

__global__ void flash_kernel(const float* __restrict__ qlat,
                             const float* __restrict__ klat,
                             float* __restrict__ x)
{
    extern __shared__ float sm[];
    float* Qs = sm;                 // 32 x 289
    float* Ks = sm + 32*FQS;        // 32 x 289
    float* Ss = sm + 64*FQS;        // 32 x 33

    const int i0 = blockIdx.x * 32;
    const int h  = blockIdx.y;
    const int b  = blockIdx.z;
    const int tid = threadIdx.x;
    const int tq = tid >> 3, c8 = tid & 7;
    const float scale = 1.0f / sqrtf(96.0f);

    // load Q tile (pre-scaled)
    for (int idx=tid; idx<32*288; idx+=256) {
        int r = idx / 288, c = idx - r*288;
        Qs[r*FQS + c] = qlat[(((size_t)b*T_SEQ + i0 + r)*NHEAD + h)*DLAT + c] * scale;
    }
    __syncthreads();

    const int i = i0 + tq;
    const float* krow = klat + ((size_t)b*T_SEQ + i)*DLAT;

    // self score (j == i)
    float part = 0.f;
    for (int c=c8; c<288; c+=8) part += Qs[tq*FQS + c] * krow[c];
    part += __shfl_xor_sync(0xffffffffu, part, 1, 8);
    part += __shfl_xor_sync(0xffffffffu, part, 2, 8);
    part += __shfl_xor_sync(0xffffffffu, part, 4, 8);

    float m = part;      // running max
    float l = 1.f;       // running sum (exp(self-m)=1)
    float acc[32];
    #pragma unroll
    for (int mi=0; mi<32; mi++) acc[mi] = krow[c8 + 8*mi];   // 1 * V_self

    // loop over odd-key tiles: key position j = 2*kk + 1
    for (int kt0 = 0; 2*kt0 + 1 < i0 + 32; kt0 += 32) {
        __syncthreads();   // protect Ks/Ss from previous iteration's readers
        for (int idx=tid; idx<32*288; idx+=256) {
            int r = idx / 288, c = idx - r*288;
            int j = 2*(kt0 + r) + 1;
            Ks[r*FQS + c] = klat[((size_t)b*T_SEQ + j)*DLAT + c];
        }
        __syncthreads();

        // scores: this thread covers keys kk = c8 + 8*jj
        float p[4];
        #pragma unroll
        for (int jj=0; jj<4; jj++) p[jj] = 0.f;
        const float* qp = Qs + tq*FQS;
        #pragma unroll 4
        for (int c=0; c<288; c++) {
            float qv = qp[c];
            #pragma unroll
            for (int jj=0; jj<4; jj++)
                p[jj] += qv * Ks[(c8 + 8*jj)*FQS + c];
        }
        #pragma unroll
        for (int jj=0; jj<4; jj++) {
            int j = 2*(kt0 + c8 + 8*jj) + 1;
            if (j >= i) p[jj] = -1e30f;
        }

        float mx = fmaxf(fmaxf(p[0],p[1]), fmaxf(p[2],p[3]));
        mx = fmaxf(mx, __shfl_xor_sync(0xffffffffu, mx, 1, 8));
        mx = fmaxf(mx, __shfl_xor_sync(0xffffffffu, mx, 2, 8));
        mx = fmaxf(mx, __shfl_xor_sync(0xffffffffu, mx, 4, 8));

        float mnew = fmaxf(m, mx);
        float corr = __expf(m - mnew);
        float psum = 0.f;
        #pragma unroll
        for (int jj=0; jj<4; jj++) { p[jj] = __expf(p[jj] - mnew); psum += p[jj]; }
        psum += __shfl_xor_sync(0xffffffffu, psum, 1, 8);
        psum += __shfl_xor_sync(0xffffffffu, psum, 2, 8);
        psum += __shfl_xor_sync(0xffffffffu, psum, 4, 8);

        l = l*corr + psum;
        m = mnew;
        #pragma unroll
        for (int mi=0; mi<32; mi++) acc[mi] *= corr;

        #pragma unroll
        for (int jj=0; jj<4; jj++) Ss[tq*33 + c8 + 8*jj] = p[jj];
        __syncthreads();

        // P @ V  (V = Ks[:, 0:256])
        #pragma unroll 4
        for (int k=0; k<32; k++) {
            float pv = Ss[tq*33 + k];
            const float* kp = Ks + k*FQS + c8;
            #pragma unroll
            for (int mi=0; mi<32; mi++) acc[mi] += pv * kp[8*mi];
        }
    }

    float inv_l = 1.f / l;
    float* xo = x + (((size_t)b*T_SEQ + i)*NHEAD + h)*256 + c8;
    #pragma unroll
    for (int mi=0; mi<32; mi++) xo[8*mi] = acc[mi] * inv_l;
}

// ---------------- host ----------------
extern "C" void kernel_launch(void* const* d_in, const int* in_sizes, int n_in,
                              void* d_out, int out_size)
{
    (void)in_sizes; (void)n_in; (void)out_size;
    const float* query    = (const float*)d_in[0];
    const float* key      = (const float*)d_in[1];
    // d_in[2] (value) is unused by the reference
    const int*   position = (const int*)d_in[3];
    const float* wq       = (const float*)d_in[4];
    const float* wkv_a    = (const float*)d_in[5];
    const float* kv_gamma = (const float*)d_in[6];
    const float* kv_beta  = (const float*)d_in[7];
    const float* wkv_b    = (const float*)d_in[8];
    const float* wo       = (const float*)d_in[9];
    const float* fc_c_w   = (const float*)d_in[10];
    const float* fc_c_b   = (const float*)d_in[11];
    const float* fc_p_w   = (const float*)d_in[12];
    const float* fc_p_b   = (const float*)d_in[13];
    float* out = (float*)d_out;

    float *kvall, *kvnorm, *q, *qlat, *klat, *c2, *p2, *x, *xv;
    cudaGetSymbolAddress((void**)&kvall,  g_kvall);
    cudaGetSymbolAddress((void**)&kvnorm, g_kvnorm);
    cudaGetSymbolAddress((void**)&q,      g_q);
    cudaGetSymbolAddress((void**)&qlat,   g_qlat);
    cudaGetSymbolAddress((void**)&klat,   g_klat);
    cudaGetSymbolAddress((void**)&c2,     g_c2);
    cudaGetSymbolAddress((void**)&p2,     g_p2);
    cudaGetSymbolAddress((void**)&x,      g_x);
    cudaGetSymbolAddress((void**)&xv,     g_xv);

    cudaFuncSetAttribute(flash_kernel, cudaFuncAttributeMaxDynamicSharedMemorySize, FLASH_SMEM);

    // 1. kv_all = key @ wkv_a           (4096 x 288 x 2048)
    sgemm_kernel<64,64,16,4,4,false><<<dim3(5,64,1),256>>>(
        ROWS,288,E_DIM, key,E_DIM,0, wkv_a,288,0, kvall,288,0, nullptr);

    // 2. layernorm + k_pe rope
    kv_post_kernel<<<ROWS,256>>>(kvall, kv_gamma, kv_beta, position, kvnorm, klat);

    // 3. q = query @ wq                 (4096 x 1536 x 2048)
    sgemm_kernel<128,128,8,8,8,false><<<dim3(12,32,1),256>>>(
        ROWS,1536,E_DIM, query,E_DIM,0, wq,1536,0, q,1536,0, nullptr);

    // 4. q_pe rope -> qlat[...,256:288]
    q_rope_kernel<<<ROWS,256>>>(q, position, qlat);

    // 5. q_abs = q_nope @ wb[h,:64,:]   per head (batched z=16)
    sgemm_kernel<64,64,16,4,4,false><<<dim3(4,64,16),256>>>(
        ROWS,256,64, q,1536,96, wkv_b,256,128*256, qlat,NHEAD*DLAT,DLAT, nullptr);

    // 6. C2 from sinusoid PE
    c2_kernel<<<1024,256>>>(fc_c_w, fc_c_b, c2);

    // 7. P2 = kv_norm @ fc_p_w + b      (4096 x 64 x 256)
    sgemm_kernel<64,64,16,4,4,false><<<dim3(1,64,1),256>>>(
        ROWS,64,256, kvnorm,256,0, fc_p_w,64,0, p2,64,0, fc_p_b);

    // 8. kv_t (sparse gated) -> klat[...,0:256]
    kvt_kernel<<<ROWS,128>>>(c2, p2, kvnorm, klat);

    // 9. flash attention over odd keys + diagonal
    flash_kernel<<<dim3(T_SEQ/32,NHEAD,B_SZ),256,FLASH_SMEM>>>(qlat, klat, x);

    // 10. xv = x @ wb[h,64:,:]^T        per head (batched, B transposed)
    sgemm_kernel<64,64,16,4,4,true><<<dim3(1,64,16),256>>>(
        ROWS,64,256, x,NHEAD*256,256, wkv_b + 64*256,256,128*256, xv,1024,64, nullptr);

    // 11. out = xv @ wo                 (4096 x 2048 x 1024)
    sgemm_kernel<128,128,8,8,8,false><<<dim3(16,32,1),256>>>(
        ROWS,E_DIM,1024, xv,1024,0, wo,E_DIM,0, out,E_DIM,0, nullptr);
}

// round 3
// speedup vs baseline: 2.0531x; 2.0531x over previous
#include <cuda_runtime.h>
#include <math.h>

// Problem constants
#define B_SZ 2
#define T_SEQ 2048
#define E_DIM 2048
#define NHEAD 16
#define NOPE 64
#define ROPE 32
#define VD 64
#define KVR 256
#define QKD 96
#define DLAT 288        // KVR + ROPE (latent dim for scores)
#define ROWS 4096       // B*T

// ---------------- scratch (device globals: allocation-free) ----------------
__device__ float g_kvall[ROWS * 288];
__device__ float g_kvnorm[ROWS * 256];
__device__ float g_q[ROWS * 1536];
__device__ float g_qlat[ROWS * NHEAD * DLAT];
__device__ float g_klat[ROWS * DLAT];
__device__ float g_c2[T_SEQ * 64];
__device__ float g_p2[ROWS * 64];
__device__ float g_x[ROWS * NHEAD * 256];
__device__ float g_xv[ROWS * 1024];
__device__ float g_wbT[NHEAD * 256 * 64];   // transposed value half of wkv_b

// ============================================================================
// TF32 tensor-core GEMM: C[M,N] = A[M,K] @ B[K,N]  (row-major, batched strides)
// Tile 128x128x32, 8 warps (warp tile 64x32), cp.async double buffer.
// Requires: M % 128 == 0, K % 32 == 0, N % 4 == 0, all pointers 16B aligned.
// ============================================================================
#define MMA_BM 128
#define MMA_BN 128
#define MMA_BK 32
#define AS_STRIDE 36     // 128 rows x (32 + pad) floats: banks (4m+k)%32 distinct
#define BS_STRIDE 136    // 32 rows x (128 + pad) floats: banks (8k+n)%32 distinct
#define STAGE_A (MMA_BM * AS_STRIDE)
#define STAGE_B (MMA_BK * BS_STRIDE)
#define MMA_SMEM (2 * (STAGE_A + STAGE_B) * 4)

__device__ __forceinline__ unsigned f2tf32(float f) {
    unsigned r; asm("cvt.rna.tf32.f32 %0, %1;" : "=r"(r) : "f"(f)); return r;
}

__global__ __launch_bounds__(256) void mma_gemm_kernel(
    int M, int N, int K,
    const float* __restrict__ A, int lda, long long sA,
    const float* __restrict__ B, int ldb, long long sB,
    float* __restrict__ C, int ldc, long long sC)
{
    extern __shared__ float smf[];
    float* As = smf;                      // [2][128][36]
    float* Bs = smf + 2 * STAGE_A;        // [2][32][136]

    A += (long long)blockIdx.z * sA;
    B += (long long)blockIdx.z * sB;
    C += (long long)blockIdx.z * sC;

    const int tid  = threadIdx.x;
    const int lane = tid & 31;
    const int wid  = tid >> 5;
    const int warp_m = (wid & 1) * 64;
    const int warp_n = (wid >> 1) * 32;
    const int bm = blockIdx.y * MMA_BM;
    const int bn = blockIdx.x * MMA_BN;

    float acc[4][4][4];
    #pragma unroll
    for (int mt = 0; mt < 4; mt++)
        #pragma unroll
        for (int nt = 0; nt < 4; nt++)
            #pragma unroll
            for (int i = 0; i < 4; i++) acc[mt][nt][i] = 0.f;

    const int nk = K / MMA_BK;

    auto load_stage = [&](int stage, int k0) {
        // A tile: 128 rows x 32 floats = 1024 x 16B chunks
        #pragma unroll
        for (int i = 0; i < 4; i++) {
            int c = tid + 256 * i;
            int row = c >> 3, col = (c & 7) * 4;
            unsigned dst = (unsigned)__cvta_generic_to_shared(
                &As[stage * STAGE_A + row * AS_STRIDE + col]);
            const float* src = A + (size_t)(bm + row) * lda + k0 + col;
            asm volatile("cp.async.cg.shared.global [%0], [%1], 16;"
                         :: "r"(dst), "l"(src));
        }
        // B tile: 32 rows x 128 floats = 1024 x 16B chunks (N-guarded, zero-fill)
        #pragma unroll
        for (int i = 0; i < 4; i++) {
            int c = tid + 256 * i;
            int k = c >> 5, col = (c & 31) * 4;
            unsigned dst = (unsigned)__cvta_generic_to_shared(
                &Bs[stage * STAGE_B + k * BS_STRIDE + col]);
            int gn = bn + col;
            bool ok = (gn < N);
            const float* src = ok ? (B + (size_t)(k0 + k) * ldb + gn) : B;
            int sz = ok ? 16 : 0;
            asm volatile("cp.async.cg.shared.global [%0], [%1], 16, %2;"
                         :: "r"(dst), "l"(src), "r"(sz));
        }
    };

    load_stage(0, 0);
    asm volatile("cp.async.commit_group;");

    for (int kt = 0; kt < nk; kt++) {
        if (kt + 1 < nk) load_stage((kt + 1) & 1, (kt + 1) * MMA_BK);
        asm volatile("cp.async.commit_group;");
        asm volatile("cp.async.wait_group 1;");
        __syncthreads();

        const float* a_s = As + (kt & 1) * STAGE_A;
        const float* b_s = Bs + (kt & 1) * STAGE_B;

        #pragma unroll
        for (int kk = 0; kk < 4; kk++) {
            const int kb = kk * 8;
            unsigned af[4][4], bf[4][2];
            #pragma unroll
            for (int mt = 0; mt < 4; mt++) {
                int r0 = warp_m + mt * 16 + (lane >> 2);
                int kc = kb + (lane & 3);
                af[mt][0] = f2tf32(a_s[r0 * AS_STRIDE + kc]);
                af[mt][1] = f2tf32(a_s[(r0 + 8) * AS_STRIDE + kc]);
                af[mt][2] = f2tf32(a_s[r0 * AS_STRIDE + kc + 4]);
                af[mt][3] = f2tf32(a_s[(r0 + 8) * AS_STRIDE + kc + 4]);
            }
            #pragma unroll
            for (int nt = 0; nt < 4; nt++) {
                int col = warp_n + nt * 8 + (lane >> 2);
                bf[nt][0] = f2tf32(b_s[(kb + (lane & 3)) * BS_STRIDE + col]);
                bf[nt][1] = f2tf32(b_s[(kb + 4 + (lane & 3)) * BS_STRIDE + col]);
            }
            #pragma unroll
            for (int mt = 0; mt < 4; mt++)
                #pragma unroll
                for (int nt = 0; nt < 4; nt++)
                    asm volatile(
                        "mma.sync.aligned.m16n8k8.row.col.f32.tf32.tf32.f32 "
                        "{%0,%1,%2,%3}, {%4,%5,%6,%7}, {%8,%9}, {%0,%1,%2,%3};"
                        : "+f"(acc[mt][nt][0]), "+f"(acc[mt][nt][1]),
                          "+f"(acc[mt][nt][2]), "+f"(acc[mt][nt][3])
                        : "r"(af[mt][0]), "r"(af[mt][1]), "r"(af[mt][2]), "r"(af[mt][3]),
                          "r"(bf[nt][0]), "r"(bf[nt][1]));
        }
        __syncthreads();
    }

    #pragma unroll
    for (int mt = 0; mt < 4; mt++) {
        #pragma unroll
        for (int nt = 0; nt < 4; nt++) {
            int r0 = bm + warp_m + mt * 16 + (lane >> 2);
            int cn = bn + warp_n + nt * 8 + (lane & 3) * 2;
            if (cn < N) {
                *(float2*)&C[(size_t)r0 * ldc + cn] =
                    make_float2(acc[mt][nt][0], acc[mt][nt][1]);
                *(float2*)&C[(size_t)(r0 + 8) * ldc + cn] =
                    make_float2(acc[mt][nt][2], acc[mt][nt][3]);
            }
        }
    }
}

// ---------------- transpose value half of wkv_b: wbT[h][c][d] = wkv_b[h*128+64+d][c]
__global__ void wbt_kernel(const float* __restrict__ wkv_b, float* __restrict__ wbT)
{
    int idx = blockIdx.x * 256 + threadIdx.x;   // 16*256*64 = 262144
    int d = idx & 63, c = (idx >> 6) & 255, h = idx >> 14;
    wbT[idx] = wkv_b[(size_t)(h * 128 + 64 + d) * 256 + c];
}

// ---------------- small FFMA SGEMM (kept for P2 only) ----------------
template<int BM,int BN,int BK,int TM,int TN>
__global__ void sgemm_kernel(int M,int N,int K,
    const float* __restrict__ A,int lda,
    const float* __restrict__ B,int ldb,
    float* __restrict__ C,int ldc,
    const float* __restrict__ bias)
{
    constexpr int THREADS=(BM/TM)*(BN/TN);
    __shared__ float As[BK][BM+1];
    __shared__ float Bs[BK][BN+1];
    const int bm = blockIdx.y*BM, bn = blockIdx.x*BN;
    const int tid = threadIdx.x;
    const int tcol = tid % (BN/TN), trow = tid / (BN/TN);
    float acc[TM][TN];
    #pragma unroll
    for (int i=0;i<TM;i++)
        #pragma unroll
        for (int j=0;j<TN;j++) acc[i][j]=0.f;

    for (int k0=0;k0<K;k0+=BK) {
        for (int idx=tid; idx<BM*BK; idx+=THREADS) {
            int m = idx / BK, kk = idx - m*BK;
            int gm = bm+m, gk = k0+kk;
            As[kk][m] = (gm<M && gk<K) ? A[(long long)gm*lda+gk] : 0.f;
        }
        for (int idx=tid; idx<BK*BN; idx+=THREADS) {
            int kk = idx / BN, n = idx - kk*BN;
            int gk = k0+kk, gn = bn+n;
            Bs[kk][n] = (gk<K && gn<N) ? B[(long long)gk*ldb+gn] : 0.f;
        }
        __syncthreads();
        #pragma unroll
        for (int kk=0;kk<BK;kk++) {
            float ra[TM], rb[TN];
            #pragma unroll
            for (int i=0;i<TM;i++) ra[i] = As[kk][trow*TM+i];
            #pragma unroll
            for (int j=0;j<TN;j++) rb[j] = Bs[kk][tcol*TN+j];
            #pragma unroll
            for (int i=0;i<TM;i++)
                #pragma unroll
                for (int j=0;j<TN;j++) acc[i][j] += ra[i]*rb[j];
        }
        __syncthreads();
    }
    #pragma unroll
    for (int i=0;i<TM;i++) {
        int gm = bm + trow*TM + i;
        if (gm >= M) continue;
        #pragma unroll
        for (int j=0;j<TN;j++) {
            int gn = bn + tcol*TN + j;
            if (gn < N) {
                float v = acc[i][j];
                if (bias) v += bias[gn];
                C[(long long)gm*ldc+gn] = v;
            }
        }
    }
}

// ---------------- kv post: layernorm(kv) + rope(k_pe) ----------------
__global__ void kv_post_kernel(const float* __restrict__ kvall,
                               const float* __restrict__ gamma,
                               const float* __restrict__ beta,
                               const int* __restrict__ position,
                               float* __restrict__ kvnorm,
                               float* __restrict__ klat)
{
    int row = blockIdx.x;
    int tid = threadIdx.x;   // 256 threads
    __shared__ float red[256];
    float v = kvall[(size_t)row*288 + tid];
    red[tid] = v;
    __syncthreads();
    for (int s=128;s>0;s>>=1){ if (tid<s) red[tid]+=red[tid+s]; __syncthreads(); }
    float mean = red[0] * (1.f/256.f);
    __syncthreads();
    float d = v - mean;
    red[tid] = d*d;
    __syncthreads();
    for (int s=128;s>0;s>>=1){ if (tid<s) red[tid]+=red[tid+s]; __syncthreads(); }
    float var = red[0] * (1.f/256.f);
    float rstd = rsqrtf(var + 1e-5f);
    kvnorm[(size_t)row*256 + tid] = d*rstd*gamma[tid] + beta[tid];

    if (tid < 16) {
        int t = row & (T_SEQ-1);
        float pos = (float)position[t];
        float freq = expf(-(float)(2*tid) * (9.2103403719761836f/32.f));
        float a = pos * freq;
        float c = cosf(a), s = sinf(a);
        float x0 = kvall[(size_t)row*288 + 256 + 2*tid];
        float x1 = kvall[(size_t)row*288 + 257 + 2*tid];
        klat[(size_t)row*288 + 256 + 2*tid] = x0*c - x1*s;
        klat[(size_t)row*288 + 257 + 2*tid] = x0*s + x1*c;
    }
}

// ---------------- rope for q_pe, write into qlat[...,256:288] ----------------
__global__ void q_rope_kernel(const float* __restrict__ q,
                              const int* __restrict__ position,
                              float* __restrict__ qlat)
{
    int row = blockIdx.x;
    int tid = threadIdx.x;          // 256 = 16 heads * 16 pairs
    int h = tid >> 4, i = tid & 15;
    int t = row & (T_SEQ-1);
    float pos = (float)position[t];
    float freq = expf(-(float)(2*i) * (9.2103403719761836f/32.f));
    float a = pos * freq;
    float c = cosf(a), s = sinf(a);
    const float* qr = q + (size_t)row*1536 + h*96 + 64;
    float x0 = qr[2*i], x1 = qr[2*i+1];
    float* o = qlat + ((size_t)row*NHEAD + h)*DLAT + 256;
    o[2*i]   = x0*c - x1*s;
    o[2*i+1] = x0*s + x1*c;
}

// ---------------- C2 = sinusoid_pe @ fc_c_w + b (rows repeated by 2) ----------------
__global__ void c2_kernel(const float* __restrict__ w,
                          const float* __restrict__ bias,
                          float* __restrict__ c2)
{
    __shared__ float pe[256];
    int p = blockIdx.x;           // 0..1023
    int tid = threadIdx.x;        // 256
    int i = tid >> 1;
    float freq = expf(-(float)(2*i) * (9.2103403719761836f/256.f));
    float a = (float)p * freq;
    pe[tid] = (tid & 1) ? cosf(a) : sinf(a);
    __syncthreads();
    if (tid < 64) {
        float acc = bias[tid];
        for (int k=0;k<256;k++) acc += pe[k]*w[k*64+tid];
        c2[(size_t)(2*p)*64 + tid]   = acc;
        c2[(size_t)(2*p+1)*64 + tid] = acc;
    }
}

// ---------------- kv_t: sparse gated combine, write klat[...,0:256] ----------------
__global__ void kvt_kernel(const float* __restrict__ c2,
                           const float* __restrict__ p2,
                           const float* __restrict__ kvnorm,
                           float* __restrict__ klat)
{
    int row = blockIdx.x;
    int tid = threadIdx.x;  // 128
    int t = row & (T_SEQ-1);
    __shared__ float r1[64], r2[64];
    if (tid < 64) {
        float a = c2[(size_t)t*64 + tid];
        r1[tid] = a * p2[(size_t)row*64 + tid];
        r2[tid] = (t & 1) ? a * p2[(size_t)(row-1)*64 + tid] : 0.f;
    }
    __syncthreads();
    for (int s=32;s>0;s>>=1){ if (tid<s){ r1[tid]+=r1[tid+s]; r2[tid]+=r2[tid+s]; } __syncthreads(); }
    float wself = 1.f/(1.f+expf(-r1[0]));
    float wprev = (t & 1) ? 1.f/(1.f+expf(-r2[0])) : 0.f;
    for (int c=tid; c<256; c+=128) {
        float v = wself * kvnorm[(size_t)row*256 + c];
        if (t & 1) v += wprev * kvnorm[(size_t)(row-1)*256 + c];
        klat[(size_t)row*288 + c] = v;
    }
}

// ---------------- flash attention over odd keys + self term ----------------
#define FQS 289
#define FLASH_SMEM ((2*32*FQS + 32*33) * 4)

__global__ void flash_kernel(const float* __restrict__ qlat,
                             const float* __restrict__ klat,
                             float* __restrict__ x)
{
    extern __shared__ float sm[];
    float* Qs = sm;                 // 32 x 289
    float* Ks = sm + 32*FQS;        // 32 x 289
    float* Ss = sm + 64*FQS;        // 32 x 33

    const int i0 = blockIdx.x * 32;
    const int h  = blockIdx.y;
    const int b  = blockIdx.z;
    const int tid = threadIdx.x;
    const int tq = tid >> 3, c8 = tid & 7;
    const float scale = 1.0f / sqrtf(96.0f);

    for (int idx=tid; idx<32*288; idx+=256) {
        int r = idx / 288, c = idx - r*288;
        Qs[r*FQS + c] = qlat[(((size_t)b*T_SEQ + i0 + r)*NHEAD + h)*DLAT + c] * scale;
    }
    __syncthreads();

    const int i = i0 + tq;
    const float* krow = klat + ((size_t)b*T_SEQ + i)*DLAT;

    float part = 0.f;
    for (int c=c8; c<288; c+=8) part += Qs[tq*FQS + c] * krow[c];
    part += __shfl_xor_sync(0xffffffffu, part, 1, 8);
    part += __shfl_xor_sync(0xffffffffu, part, 2, 8);
    part += __shfl_xor_sync(0xffffffffu, part, 4, 8);

    float m = part;
    float l = 1.f;
    float acc[32];
    #pragma unroll
    for (int mi=0; mi<32; mi++) acc[mi] = krow[c8 + 8*mi];

    for (int kt0 = 0; 2*kt0 + 1 < i0 + 32; kt0 += 32) {
        __syncthreads();
        for (int idx=tid; idx<32*288; idx+=256) {
            int r = idx / 288, c = idx - r*288;
            int j = 2*(kt0 + r) + 1;
            Ks[r*FQS + c] = klat[((size_t)b*T_SEQ + j)*DLAT + c];
        }
        __syncthreads();

        float p[4];
        #pragma unroll
        for (int jj=0; jj<4; jj++) p[jj] = 0.f;
        const float* qp = Qs + tq*FQS;
        #pragma unroll 4
        for (int c=0; c<288; c++) {
            float qv = qp[c];
            #pragma unroll
            for (int jj=0; jj<4; jj++)
                p[jj] += qv * Ks[(c8 + 8*jj)*FQS + c];
        }
        #pragma unroll
        for (int jj=0; jj<4; jj++) {
            int j = 2*(kt0 + c8 + 8*jj) + 1;
            if (j >= i) p[jj] = -1e30f;
        }

        float mx = fmaxf(fmaxf(p[0],p[1]), fmaxf(p[2],p[3]));
        mx = fmaxf(mx, __shfl_xor_sync(0xffffffffu, mx, 1, 8));
        mx = fmaxf(mx, __shfl_xor_sync(0xffffffffu, mx, 2, 8));
        mx = fmaxf(mx, __shfl_xor_sync(0xffffffffu, mx, 4, 8));

        float mnew = fmaxf(m, mx);
        float corr = __expf(m - mnew);
        float psum = 0.f;
        #pragma unroll
        for (int jj=0; jj<4; jj++) { p[jj] = __expf(p[jj] - mnew); psum += p[jj]; }
        psum += __shfl_xor_sync(0xffffffffu, psum, 1, 8);
        psum += __shfl_xor_sync(0xffffffffu, psum, 2, 8);
        psum += __shfl_xor_sync(0xffffffffu, psum, 4, 8);

        l = l*corr + psum;
        m = mnew;
        #pragma unroll
        for (int mi=0; mi<32; mi++) acc[mi] *= corr;

        #pragma unroll
        for (int jj=0; jj<4; jj++) Ss[tq*33 + c8 + 8*jj] = p[jj];
        __syncthreads();

        #pragma unroll 4
        for (int k=0; k<32; k++) {
            float pv = Ss[tq*33 + k];
            const float* kp = Ks + k*FQS + c8;
            #pragma unroll
            for (int mi=0; mi<32; mi++) acc[mi] += pv * kp[8*mi];
        }
    }

    float inv_l = 1.f / l;
    float* xo = x + (((size_t)b*T_SEQ + i)*NHEAD + h)*256 + c8;
    #pragma unroll
    for (int mi=0; mi<32; mi++) xo[8*mi] = acc[mi] * inv_l;
}

// ---------------- host ----------------
extern "C" void kernel_launch(void* const* d_in, const int* in_sizes, int n_in,
                              void* d_out, int out_size)
{
    (void)in_sizes; (void)n_in; (void)out_size;
    const float* query    = (const float*)d_in[0];
    const float* key      = (const float*)d_in[1];
    const int*   position = (const int*)d_in[3];
    const float* wq       = (const float*)d_in[4];
    const float* wkv_a    = (const float*)d_in[5];
    const float* kv_gamma = (const float*)d_in[6];
    const float* kv_beta  = (const float*)d_in[7];
    const float* wkv_b    = (const float*)d_in[8];
    const float* wo       = (const float*)d_in[9];
    const float* fc_c_w   = (const float*)d_in[10];
    const float* fc_c_b   = (const float*)d_in[11];
    const float* fc_p_w   = (const float*)d_in[12];
    const float* fc_p_b   = (const float*)d_in[13];
    float* out = (float*)d_out;

    float *kvall, *kvnorm, *q, *qlat, *klat, *c2, *p2, *x, *xv, *wbT;
    cudaGetSymbolAddress((void**)&kvall,  g_kvall);
    cudaGetSymbolAddress((void**)&kvnorm, g_kvnorm);
    cudaGetSymbolAddress((void**)&q,      g_q);
    cudaGetSymbolAddress((void**)&qlat,   g_qlat);
    cudaGetSymbolAddress((void**)&klat,   g_klat);
    cudaGetSymbolAddress((void**)&c2,     g_c2);
    cudaGetSymbolAddress((void**)&p2,     g_p2);
    cudaGetSymbolAddress((void**)&x,      g_x);
    cudaGetSymbolAddress((void**)&xv,     g_xv);
    cudaGetSymbolAddress((void**)&wbT,    g_wbT);

    cudaFuncSetAttribute(flash_kernel, cudaFuncAttributeMaxDynamicSharedMemorySize, FLASH_SMEM);
    cudaFuncSetAttribute(mma_gemm_kernel, cudaFuncAttributeMaxDynamicSharedMemorySize, MMA_SMEM);

    // 0. transpose wkv_b value half (independent)
    wbt_kernel<<<1024,256>>>(wkv_b, wbT);

    // 1. kv_all = key @ wkv_a           (4096 x 288 x 2048)  [tf32 mma]
    mma_gemm_kernel<<<dim3(3,32,1),256,MMA_SMEM>>>(
        ROWS,288,E_DIM, key,E_DIM,0, wkv_a,288,0, kvall,288,0);

    // 2. layernorm + k_pe rope
    kv_post_kernel<<<ROWS,256>>>(kvall, kv_gamma, kv_beta, position, kvnorm, klat);

    // 3. q = query @ wq                 (4096 x 1536 x 2048)  [tf32 mma]
    mma_gemm_kernel<<<dim3(12,32,1),256,MMA_SMEM>>>(
        ROWS,1536,E_DIM, query,E_DIM,0, wq,1536,0, q,1536,0);

    // 4. q_pe rope -> qlat[...,256:288]
    q_rope_kernel<<<ROWS,256>>>(q, position, qlat);

    // 5. q_abs = q_nope @ wb[h,:64,:]   (batched z=16)  [tf32 mma]
    mma_gemm_kernel<<<dim3(2,32,NHEAD),256,MMA_SMEM>>>(
        ROWS,256,64, q,1536,96, wkv_b,256,128*256, qlat,NHEAD*DLAT,DLAT);

    // 6. C2 from sinusoid PE
    c2_kernel<<<1024,256>>>(fc_c_w, fc_c_b, c2);

    // 7. P2 = kv_norm @ fc_p_w + b      (4096 x 64 x 256)  [ffma, tiny]
    sgemm_kernel<64,64,16,4,4><<<dim3(1,64,1),256>>>(
        ROWS,64,256, kvnorm,256, fc_p_w,64, p2,64, fc_p_b);

    // 8. kv_t (sparse gated) -> klat[...,0:256]
    kvt_kernel<<<ROWS,128>>>(c2, p2, kvnorm, klat);

    // 9. flash attention over odd keys + diagonal
    flash_kernel<<<dim3(T_SEQ/32,NHEAD,B_SZ),256,FLASH_SMEM>>>(qlat, klat, x);

    // 10. xv = x @ wbT[h]               (batched z=16, K=256, N=64)  [tf32 mma]
    mma_gemm_kernel<<<dim3(1,32,NHEAD),256,MMA_SMEM>>>(
        ROWS,64,256, x,NHEAD*256,256, wbT,64,256*64, xv,1024,64);

    // 11. out = xv @ wo                 (4096 x 2048 x 1024)  [tf32 mma]
    mma_gemm_kernel<<<dim3(16,32,1),256,MMA_SMEM>>>(
        ROWS,E_DIM,1024, xv,1024,0, wo,E_DIM,0, out,E_DIM,0);
}

// round 4
// speedup vs baseline: 6.4810x; 3.1567x over previous
#include <cuda_runtime.h>
#include <math.h>

// Problem constants
#define B_SZ 2
#define T_SEQ 2048
#define E_DIM 2048
#define NHEAD 16
#define NOPE 64
#define ROPE 32
#define VD 64
#define KVR 256
#define QKD 96
#define DLAT 288        // KVR + ROPE (latent dim for scores)
#define ROWS 4096       // B*T

// ---------------- scratch (device globals: allocation-free) ----------------
__device__ float g_kvall[ROWS * 288];
__device__ float g_kvnorm[ROWS * 256];
__device__ float g_q[ROWS * 1536];
__device__ float g_qlat[ROWS * NHEAD * DLAT];
__device__ float g_klat[ROWS * DLAT];
__device__ float g_c2[T_SEQ * 64];
__device__ float g_p2[ROWS * 64];
__device__ float g_x[ROWS * NHEAD * 256];
__device__ float g_xv[ROWS * 1024];
__device__ float g_wbT[NHEAD * 256 * 64];   // transposed value half of wkv_b

__device__ __forceinline__ unsigned f2tf32(float f) {
    unsigned r; asm("cvt.rna.tf32.f32 %0, %1;" : "=r"(r) : "f"(f)); return r;
}

// ============================================================================
// TF32 tensor-core GEMM: C[M,N] = A[M,K] @ B[K,N]  (row-major, batched strides)
// ============================================================================
#define MMA_BM 128
#define MMA_BN 128
#define MMA_BK 32
#define AS_STRIDE 36
#define BS_STRIDE 136
#define STAGE_A (MMA_BM * AS_STRIDE)
#define STAGE_B (MMA_BK * BS_STRIDE)
#define MMA_SMEM (2 * (STAGE_A + STAGE_B) * 4)

__global__ __launch_bounds__(256) void mma_gemm_kernel(
    int M, int N, int K,
    const float* __restrict__ A, int lda, long long sA,
    const float* __restrict__ B, int ldb, long long sB,
    float* __restrict__ C, int ldc, long long sC)
{
    extern __shared__ float smf[];
    float* As = smf;
    float* Bs = smf + 2 * STAGE_A;

    A += (long long)blockIdx.z * sA;
    B += (long long)blockIdx.z * sB;
    C += (long long)blockIdx.z * sC;

    const int tid  = threadIdx.x;
    const int lane = tid & 31;
    const int wid  = tid >> 5;
    const int warp_m = (wid & 1) * 64;
    const int warp_n = (wid >> 1) * 32;
    const int bm = blockIdx.y * MMA_BM;
    const int bn = blockIdx.x * MMA_BN;

    float acc[4][4][4];
    #pragma unroll
    for (int mt = 0; mt < 4; mt++)
        #pragma unroll
        for (int nt = 0; nt < 4; nt++)
            #pragma unroll
            for (int i = 0; i < 4; i++) acc[mt][nt][i] = 0.f;

    const int nk = K / MMA_BK;

    auto load_stage = [&](int stage, int k0) {
        #pragma unroll
        for (int i = 0; i < 4; i++) {
            int c = tid + 256 * i;
            int row = c >> 3, col = (c & 7) * 4;
            unsigned dst = (unsigned)__cvta_generic_to_shared(
                &As[stage * STAGE_A + row * AS_STRIDE + col]);
            const float* src = A + (size_t)(bm + row) * lda + k0 + col;
            asm volatile("cp.async.cg.shared.global [%0], [%1], 16;"
                         :: "r"(dst), "l"(src));
        }
        #pragma unroll
        for (int i = 0; i < 4; i++) {
            int c = tid + 256 * i;
            int k = c >> 5, col = (c & 31) * 4;
            unsigned dst = (unsigned)__cvta_generic_to_shared(
                &Bs[stage * STAGE_B + k * BS_STRIDE + col]);
            int gn = bn + col;
            bool ok = (gn < N);
            const float* src = ok ? (B + (size_t)(k0 + k) * ldb + gn) : B;
            int sz = ok ? 16 : 0;
            asm volatile("cp.async.cg.shared.global [%0], [%1], 16, %2;"
                         :: "r"(dst), "l"(src), "r"(sz));
        }
    };

    load_stage(0, 0);
    asm volatile("cp.async.commit_group;");

    for (int kt = 0; kt < nk; kt++) {
        if (kt + 1 < nk) load_stage((kt + 1) & 1, (kt + 1) * MMA_BK);
        asm volatile("cp.async.commit_group;");
        asm volatile("cp.async.wait_group 1;");
        __syncthreads();

        const float* a_s = As + (kt & 1) * STAGE_A;
        const float* b_s = Bs + (kt & 1) * STAGE_B;

        #pragma unroll
        for (int kk = 0; kk < 4; kk++) {
            const int kb = kk * 8;
            unsigned af[4][4], bf[4][2];
            #pragma unroll
            for (int mt = 0; mt < 4; mt++) {
                int r0 = warp_m + mt * 16 + (lane >> 2);
                int kc = kb + (lane & 3);
                af[mt][0] = f2tf32(a_s[r0 * AS_STRIDE + kc]);
                af[mt][1] = f2tf32(a_s[(r0 + 8) * AS_STRIDE + kc]);
                af[mt][2] = f2tf32(a_s[r0 * AS_STRIDE + kc + 4]);
                af[mt][3] = f2tf32(a_s[(r0 + 8) * AS_STRIDE + kc + 4]);
            }
            #pragma unroll
            for (int nt = 0; nt < 4; nt++) {
                int col = warp_n + nt * 8 + (lane >> 2);
                bf[nt][0] = f2tf32(b_s[(kb + (lane & 3)) * BS_STRIDE + col]);
                bf[nt][1] = f2tf32(b_s[(kb + 4 + (lane & 3)) * BS_STRIDE + col]);
            }
            #pragma unroll
            for (int mt = 0; mt < 4; mt++)
                #pragma unroll
                for (int nt = 0; nt < 4; nt++)
                    asm volatile(
                        "mma.sync.aligned.m16n8k8.row.col.f32.tf32.tf32.f32 "
                        "{%0,%1,%2,%3}, {%4,%5,%6,%7}, {%8,%9}, {%0,%1,%2,%3};"
                        : "+f"(acc[mt][nt][0]), "+f"(acc[mt][nt][1]),
                          "+f"(acc[mt][nt][2]), "+f"(acc[mt][nt][3])
                        : "r"(af[mt][0]), "r"(af[mt][1]), "r"(af[mt][2]), "r"(af[mt][3]),
                          "r"(bf[nt][0]), "r"(bf[nt][1]));
        }
        __syncthreads();
    }

    #pragma unroll
    for (int mt = 0; mt < 4; mt++) {
        #pragma unroll
        for (int nt = 0; nt < 4; nt++) {
            int r0 = bm + warp_m + mt * 16 + (lane >> 2);
            int cn = bn + warp_n + nt * 8 + (lane & 3) * 2;
            if (cn < N) {
                *(float2*)&C[(size_t)r0 * ldc + cn] =
                    make_float2(acc[mt][nt][0], acc[mt][nt][1]);
                *(float2*)&C[(size_t)(r0 + 8) * ldc + cn] =
                    make_float2(acc[mt][nt][2], acc[mt][nt][3]);
            }
        }
    }
}

// ---------------- transpose value half of wkv_b ----------------
__global__ void wbt_kernel(const float* __restrict__ wkv_b, float* __restrict__ wbT)
{
    int idx = blockIdx.x * 256 + threadIdx.x;
    int d = idx & 63, c = (idx >> 6) & 255, h = idx >> 14;
    wbT[idx] = wkv_b[(size_t)(h * 128 + 64 + d) * 256 + c];
}

// ---------------- small FFMA SGEMM (P2 only) ----------------
template<int BM,int BN,int BK,int TM,int TN>
__global__ void sgemm_kernel(int M,int N,int K,
    const float* __restrict__ A,int lda,
    const float* __restrict__ B,int ldb,
    float* __restrict__ C,int ldc,
    const float* __restrict__ bias)
{
    constexpr int THREADS=(BM/TM)*(BN/TN);
    __shared__ float As[BK][BM+1];
    __shared__ float Bs[BK][BN+1];
    const int bm = blockIdx.y*BM, bn = blockIdx.x*BN;
    const int tid = threadIdx.x;
    const int tcol = tid % (BN/TN), trow = tid / (BN/TN);
    float acc[TM][TN];
    #pragma unroll
    for (int i=0;i<TM;i++)
        #pragma unroll
        for (int j=0;j<TN;j++) acc[i][j]=0.f;

    for (int k0=0;k0<K;k0+=BK) {
        for (int idx=tid; idx<BM*BK; idx+=THREADS) {
            int m = idx / BK, kk = idx - m*BK;
            int gm = bm+m, gk = k0+kk;
            As[kk][m] = (gm<M && gk<K) ? A[(long long)gm*lda+gk] : 0.f;
        }
        for (int idx=tid; idx<BK*BN; idx+=THREADS) {
            int kk = idx / BN, n = idx - kk*BN;
            int gk = k0+kk, gn = bn+n;
            Bs[kk][n] = (gk<K && gn<N) ? B[(long long)gk*ldb+gn] : 0.f;
        }
        __syncthreads();
        #pragma unroll
        for (int kk=0;kk<BK;kk++) {
            float ra[TM], rb[TN];
            #pragma unroll
            for (int i=0;i<TM;i++) ra[i] = As[kk][trow*TM+i];
            #pragma unroll
            for (int j=0;j<TN;j++) rb[j] = Bs[kk][tcol*TN+j];
            #pragma unroll
            for (int i=0;i<TM;i++)
                #pragma unroll
                for (int j=0;j<TN;j++) acc[i][j] += ra[i]*rb[j];
        }
        __syncthreads();
    }
    #pragma unroll
    for (int i=0;i<TM;i++) {
        int gm = bm + trow*TM + i;
        if (gm >= M) continue;
        #pragma unroll
        for (int j=0;j<TN;j++) {
            int gn = bn + tcol*TN + j;
            if (gn < N) {
                float v = acc[i][j];
                if (bias) v += bias[gn];
                C[(long long)gm*ldc+gn] = v;
            }
        }
    }
}

// ---------------- kv post: layernorm(kv) + rope(k_pe) ----------------
__global__ void kv_post_kernel(const float* __restrict__ kvall,
                               const float* __restrict__ gamma,
                               const float* __restrict__ beta,
                               const int* __restrict__ position,
                               float* __restrict__ kvnorm,
                               float* __restrict__ klat)
{
    int row = blockIdx.x;
    int tid = threadIdx.x;
    __shared__ float red[256];
    float v = kvall[(size_t)row*288 + tid];
    red[tid] = v;
    __syncthreads();
    for (int s=128;s>0;s>>=1){ if (tid<s) red[tid]+=red[tid+s]; __syncthreads(); }
    float mean = red[0] * (1.f/256.f);
    __syncthreads();
    float d = v - mean;
    red[tid] = d*d;
    __syncthreads();
    for (int s=128;s>0;s>>=1){ if (tid<s) red[tid]+=red[tid+s]; __syncthreads(); }
    float var = red[0] * (1.f/256.f);
    float rstd = rsqrtf(var + 1e-5f);
    kvnorm[(size_t)row*256 + tid] = d*rstd*gamma[tid] + beta[tid];

    if (tid < 16) {
        int t = row & (T_SEQ-1);
        float pos = (float)position[t];
        float freq = expf(-(float)(2*tid) * (9.2103403719761836f/32.f));
        float a = pos * freq;
        float c = cosf(a), s = sinf(a);
        float x0 = kvall[(size_t)row*288 + 256 + 2*tid];
        float x1 = kvall[(size_t)row*288 + 257 + 2*tid];
        klat[(size_t)row*288 + 256 + 2*tid] = x0*c - x1*s;
        klat[(size_t)row*288 + 257 + 2*tid] = x0*s + x1*c;
    }
}

// ---------------- rope for q_pe ----------------
__global__ void q_rope_kernel(const float* __restrict__ q,
                              const int* __restrict__ position,
                              float* __restrict__ qlat)
{
    int row = blockIdx.x;
    int tid = threadIdx.x;
    int h = tid >> 4, i = tid & 15;
    int t = row & (T_SEQ-1);
    float pos = (float)position[t];
    float freq = expf(-(float)(2*i) * (9.2103403719761836f/32.f));
    float a = pos * freq;
    float c = cosf(a), s = sinf(a);
    const float* qr = q + (size_t)row*1536 + h*96 + 64;
    float x0 = qr[2*i], x1 = qr[2*i+1];
    float* o = qlat + ((size_t)row*NHEAD + h)*DLAT + 256;
    o[2*i]   = x0*c - x1*s;
    o[2*i+1] = x0*s + x1*c;
}

// ---------------- C2 ----------------
__global__ void c2_kernel(const float* __restrict__ w,
                          const float* __restrict__ bias,
                          float* __restrict__ c2)
{
    __shared__ float pe[256];
    int p = blockIdx.x;
    int tid = threadIdx.x;
    int i = tid >> 1;
    float freq = expf(-(float)(2*i) * (9.2103403719761836f/256.f));
    float a = (float)p * freq;
    pe[tid] = (tid & 1) ? cosf(a) : sinf(a);
    __syncthreads();
    if (tid < 64) {
        float acc = bias[tid];
        for (int k=0;k<256;k++) acc += pe[k]*w[k*64+tid];
        c2[(size_t)(2*p)*64 + tid]   = acc;
        c2[(size_t)(2*p+1)*64 + tid] = acc;
    }
}

// ---------------- kv_t gated combine ----------------
__global__ void kvt_kernel(const float* __restrict__ c2,
                           const float* __restrict__ p2,
                           const float* __restrict__ kvnorm,
                           float* __restrict__ klat)
{
    int row = blockIdx.x;
    int tid = threadIdx.x;
    int t = row & (T_SEQ-1);
    __shared__ float r1[64], r2[64];
    if (tid < 64) {
        float a = c2[(size_t)t*64 + tid];
        r1[tid] = a * p2[(size_t)row*64 + tid];
        r2[tid] = (t & 1) ? a * p2[(size_t)(row-1)*64 + tid] : 0.f;
    }
    __syncthreads();
    for (int s=32;s>0;s>>=1){ if (tid<s){ r1[tid]+=r1[tid+s]; r2[tid]+=r2[tid+s]; } __syncthreads(); }
    float wself = 1.f/(1.f+expf(-r1[0]));
    float wprev = (t & 1) ? 1.f/(1.f+expf(-r2[0])) : 0.f;
    for (int c=tid; c<256; c+=128) {
        float v = wself * kvnorm[(size_t)row*256 + c];
        if (t & 1) v += wprev * kvnorm[(size_t)(row-1)*256 + c];
        klat[(size_t)row*288 + c] = v;
    }
}

// ============================================================================
// Tensor-core flash attention over odd keys + self term (tf32 mma)
// Block: 256 threads, BQ=64 queries of one (b,h). 8 warps = 4 bands x 2 halves.
// K/V tile: 32 odd keys x 288 (V = cols 0:256), double-buffered cp.async.
// ============================================================================
#define BQ 64
#define QS 292      // padded stride for Q/K smem rows
#define SS 36       // padded stride for S/P smem
#define FLASH_SMEM ((128*QS + BQ*SS + 3*BQ) * 4)

__global__ __launch_bounds__(256, 1) void flash_mma_kernel(
    const float* __restrict__ qlat,
    const float* __restrict__ klat,
    float* __restrict__ x)
{
    extern __shared__ float sm[];
    float* Qs   = sm;                       // 64 x 292
    float* Ks   = sm + 64*QS;               // 2 x 32 x 292
    float* Ssm  = sm + 128*QS;              // 64 x 36
    float* Mrow = Ssm + BQ*SS;              // 64
    float* Lrow = Mrow + BQ;                // 64
    float* Crow = Lrow + BQ;                // 64

    const int i0 = blockIdx.x * BQ;
    const int h  = blockIdx.y;
    const int b  = blockIdx.z;
    const int tid  = threadIdx.x;
    const int lane = tid & 31;
    const int wid  = tid >> 5;
    const int band = wid >> 1;       // 0..3: query rows band*16..+16
    const int half = wid & 1;        // 0/1: S cols half*16, V cols half*128
    const int gid  = lane >> 2;      // group id 0..7
    const int tig  = lane & 3;       // thread in group
    const float scale = 0.10206207261596575f;  // 1/sqrt(96)

    // ---- Q tile cp.async (unscaled; scale folded into softmax) ----
    const float* qbase = qlat + (((size_t)b*T_SEQ + i0)*NHEAD + h)*DLAT;
    #pragma unroll
    for (int i = 0; i < 18; i++) {
        int c = tid + 256*i;               // 0..4607
        int r = c / 72, c4 = c % 72;
        unsigned dst = (unsigned)__cvta_generic_to_shared(&Qs[r*QS + c4*4]);
        const float* src = qbase + (size_t)r*(NHEAD*DLAT) + c4*4;
        asm volatile("cp.async.cg.shared.global [%0], [%1], 16;" :: "r"(dst), "l"(src));
    }
    asm volatile("cp.async.commit_group;");

    auto load_k = [&](int stage, int kt0) {
        #pragma unroll
        for (int i = 0; i < 9; i++) {
            int c = tid + 256*i;           // 0..2303
            int r = c / 72, c4 = c % 72;
            int j = 2*(kt0 + r) + 1;
            if (j > T_SEQ-1) j = T_SEQ-1;  // clamp (masked later)
            unsigned dst = (unsigned)__cvta_generic_to_shared(&Ks[stage*32*QS + r*QS + c4*4]);
            const float* src = klat + ((size_t)b*T_SEQ + j)*DLAT + c4*4;
            asm volatile("cp.async.cg.shared.global [%0], [%1], 16;" :: "r"(dst), "l"(src));
        }
    };
    load_k(0, 0);
    asm volatile("cp.async.commit_group;");

    // wait for Q (leave K0 in flight)
    asm volatile("cp.async.wait_group 1;");
    __syncthreads();

    // ---- self score + softmax state init ----
    {
        int row = tid >> 2, cg = tid & 3;
        const float* kself = klat + ((size_t)b*T_SEQ + i0 + row)*DLAT;
        float part = 0.f;
        #pragma unroll 8
        for (int k = 0; k < 72; k++) {
            int c = 4*k + cg;
            part += Qs[row*QS + c] * kself[c];
        }
        part += __shfl_xor_sync(0xffffffffu, part, 1, 4);
        part += __shfl_xor_sync(0xffffffffu, part, 2, 4);
        if (cg == 0) { Mrow[row] = part * scale; Lrow[row] = 1.f; }
    }

    // ---- O accumulator init = V_self ----
    float o[16][4];
    {
        int r1 = i0 + band*16 + gid;
        const float* v1 = klat + ((size_t)b*T_SEQ + r1)*DLAT;
        const float* v2 = klat + ((size_t)b*T_SEQ + r1 + 8)*DLAT;
        #pragma unroll
        for (int nt = 0; nt < 16; nt++) {
            int col = half*128 + nt*8 + tig*2;
            float2 a = *(const float2*)&v1[col];
            float2 c = *(const float2*)&v2[col];
            o[nt][0] = a.x; o[nt][1] = a.y; o[nt][2] = c.x; o[nt][3] = c.y;
        }
    }
    __syncthreads();   // Mrow/Lrow visible

    // ---- key-tile loop ----
    int stage = 0;
    for (int kt0 = 0; 2*kt0 + 1 < i0 + BQ; kt0 += 32) {
        bool more = (2*(kt0+32) + 1 < i0 + BQ);
        if (more) load_k(stage ^ 1, kt0 + 32);
        asm volatile("cp.async.commit_group;");
        asm volatile("cp.async.wait_group 1;");
        __syncthreads();

        const float* ks = Ks + stage*32*QS;

        // QK^T: warp computes 16x16 of S (band rows, half*16 cols)
        float sf[2][4];
        #pragma unroll
        for (int nt = 0; nt < 2; nt++)
            #pragma unroll
            for (int i = 0; i < 4; i++) sf[nt][i] = 0.f;
        {
            const float* qb = Qs + (band*16)*QS;
            const float* kb = ks + (half*16)*QS;
            #pragma unroll 4
            for (int kst = 0; kst < 36; kst++) {
                int kc = kst*8 + tig;
                unsigned a0 = f2tf32(qb[gid*QS + kc]);
                unsigned a1 = f2tf32(qb[(gid+8)*QS + kc]);
                unsigned a2 = f2tf32(qb[gid*QS + kc + 4]);
                unsigned a3 = f2tf32(qb[(gid+8)*QS + kc + 4]);
                #pragma unroll
                for (int nt = 0; nt < 2; nt++) {
                    unsigned b0 = f2tf32(kb[(nt*8+gid)*QS + kc]);
                    unsigned b1 = f2tf32(kb[(nt*8+gid)*QS + kc + 4]);
                    asm volatile(
                        "mma.sync.aligned.m16n8k8.row.col.f32.tf32.tf32.f32 "
                        "{%0,%1,%2,%3}, {%4,%5,%6,%7}, {%8,%9}, {%0,%1,%2,%3};"
                        : "+f"(sf[nt][0]), "+f"(sf[nt][1]), "+f"(sf[nt][2]), "+f"(sf[nt][3])
                        : "r"(a0), "r"(a1), "r"(a2), "r"(a3), "r"(b0), "r"(b1));
                }
            }
        }
        // stage S to smem
        #pragma unroll
        for (int nt = 0; nt < 2; nt++) {
            int r = band*16 + gid;
            int c = half*16 + nt*8 + tig*2;
            *(float2*)&Ssm[r*SS + c]     = make_float2(sf[nt][0], sf[nt][1]);
            *(float2*)&Ssm[(r+8)*SS + c] = make_float2(sf[nt][2], sf[nt][3]);
        }
        __syncthreads();

        // online softmax: 4 threads per row, 8 cols each
        {
            int row = tid >> 2, cg = tid & 3;
            int iq = i0 + row;
            float vals[8];
            float mx = -1e30f;
            #pragma unroll
            for (int jj = 0; jj < 8; jj++) {
                int col = cg*8 + jj;
                int j = 2*(kt0 + col) + 1;
                float s = (j < iq) ? Ssm[row*SS + col]*scale : -1e30f;
                vals[jj] = s;
                mx = fmaxf(mx, s);
            }
            mx = fmaxf(mx, __shfl_xor_sync(0xffffffffu, mx, 1, 4));
            mx = fmaxf(mx, __shfl_xor_sync(0xffffffffu, mx, 2, 4));
            float mprev = Mrow[row];
            float mnew = fmaxf(mprev, mx);
            float corr = __expf(mprev - mnew);
            float sum = 0.f;
            #pragma unroll
            for (int jj = 0; jj < 8; jj++) {
                float e = __expf(vals[jj] - mnew);
                Ssm[row*SS + cg*8 + jj] = e;
                sum += e;
            }
            sum += __shfl_xor_sync(0xffffffffu, sum, 1, 4);
            sum += __shfl_xor_sync(0xffffffffu, sum, 2, 4);
            if (cg == 0) {
                Mrow[row] = mnew;
                Lrow[row] = Lrow[row]*corr + sum;
                Crow[row] = corr;
            }
        }
        __syncthreads();

        // scale O, then P @ V
        {
            float c1 = Crow[band*16 + gid];
            float c2v = Crow[band*16 + gid + 8];
            #pragma unroll
            for (int nt = 0; nt < 16; nt++) {
                o[nt][0] *= c1; o[nt][1] *= c1;
                o[nt][2] *= c2v; o[nt][3] *= c2v;
            }
            const float* pb = Ssm + (band*16)*SS;
            #pragma unroll
            for (int kst = 0; kst < 4; kst++) {
                int kc = kst*8 + tig;
                unsigned a0 = f2tf32(pb[gid*SS + kc]);
                unsigned a1 = f2tf32(pb[(gid+8)*SS + kc]);
                unsigned a2 = f2tf32(pb[gid*SS + kc + 4]);
                unsigned a3 = f2tf32(pb[(gid+8)*SS + kc + 4]);
                #pragma unroll
                for (int nt = 0; nt < 16; nt++) {
                    int vc = half*128 + nt*8 + gid;
                    unsigned b0 = f2tf32(ks[(kst*8 + tig)*QS + vc]);
                    unsigned b1 = f2tf32(ks[(kst*8 + tig + 4)*QS + vc]);
                    asm volatile(
                        "mma.sync.aligned.m16n8k8.row.col.f32.tf32.tf32.f32 "
                        "{%0,%1,%2,%3}, {%4,%5,%6,%7}, {%8,%9}, {%0,%1,%2,%3};"
                        : "+f"(o[nt][0]), "+f"(o[nt][1]), "+f"(o[nt][2]), "+f"(o[nt][3])
                        : "r"(a0), "r"(a1), "r"(a2), "r"(a3), "r"(b0), "r"(b1));
                }
            }
        }
        __syncthreads();
        stage ^= 1;
    }

    // ---- epilogue: normalize and store ----
    {
        int r1 = i0 + band*16 + gid;
        float li1 = 1.f / Lrow[band*16 + gid];
        float li2 = 1.f / Lrow[band*16 + gid + 8];
        float* x1 = x + (((size_t)b*T_SEQ + r1)*NHEAD + h)*256;
        float* x2 = x + (((size_t)b*T_SEQ + r1 + 8)*NHEAD + h)*256;
        #pragma unroll
        for (int nt = 0; nt < 16; nt++) {
            int col = half*128 + nt*8 + tig*2;
            *(float2*)&x1[col] = make_float2(o[nt][0]*li1, o[nt][1]*li1);
            *(float2*)&x2[col] = make_float2(o[nt][2]*li2, o[nt][3]*li2);
        }
    }
}

// ---------------- host ----------------
extern "C" void kernel_launch(void* const* d_in, const int* in_sizes, int n_in,
                              void* d_out, int out_size)
{
    (void)in_sizes; (void)n_in; (void)out_size;
    const float* query    = (const float*)d_in[0];
    const float* key      = (const float*)d_in[1];
    const int*   position = (const int*)d_in[3];
    const float* wq       = (const float*)d_in[4];
    const float* wkv_a    = (const float*)d_in[5];
    const float* kv_gamma = (const float*)d_in[6];
    const float* kv_beta  = (const float*)d_in[7];
    const float* wkv_b    = (const float*)d_in[8];
    const float* wo       = (const float*)d_in[9];
    const float* fc_c_w   = (const float*)d_in[10];
    const float* fc_c_b   = (const float*)d_in[11];
    const float* fc_p_w   = (const float*)d_in[12];
    const float* fc_p_b   = (const float*)d_in[13];
    float* out = (float*)d_out;

    float *kvall, *kvnorm, *q, *qlat, *klat, *c2, *p2, *x, *xv, *wbT;
    cudaGetSymbolAddress((void**)&kvall,  g_kvall);
    cudaGetSymbolAddress((void**)&kvnorm, g_kvnorm);
    cudaGetSymbolAddress((void**)&q,      g_q);
    cudaGetSymbolAddress((void**)&qlat,   g_qlat);
    cudaGetSymbolAddress((void**)&klat,   g_klat);
    cudaGetSymbolAddress((void**)&c2,     g_c2);
    cudaGetSymbolAddress((void**)&p2,     g_p2);
    cudaGetSymbolAddress((void**)&x,      g_x);
    cudaGetSymbolAddress((void**)&xv,     g_xv);
    cudaGetSymbolAddress((void**)&wbT,    g_wbT);

    cudaFuncSetAttribute(flash_mma_kernel, cudaFuncAttributeMaxDynamicSharedMemorySize, FLASH_SMEM);
    cudaFuncSetAttribute(mma_gemm_kernel, cudaFuncAttributeMaxDynamicSharedMemorySize, MMA_SMEM);

    // 0. transpose wkv_b value half
    wbt_kernel<<<1024,256>>>(wkv_b, wbT);

    // 1. kv_all = key @ wkv_a           (4096 x 288 x 2048)
    mma_gemm_kernel<<<dim3(3,32,1),256,MMA_SMEM>>>(
        ROWS,288,E_DIM, key,E_DIM,0, wkv_a,288,0, kvall,288,0);

    // 2. layernorm + k_pe rope
    kv_post_kernel<<<ROWS,256>>>(kvall, kv_gamma, kv_beta, position, kvnorm, klat);

    // 3. q = query @ wq                 (4096 x 1536 x 2048)
    mma_gemm_kernel<<<dim3(12,32,1),256,MMA_SMEM>>>(
        ROWS,1536,E_DIM, query,E_DIM,0, wq,1536,0, q,1536,0);

    // 4. q_pe rope
    q_rope_kernel<<<ROWS,256>>>(q, position, qlat);

    // 5. q_abs = q_nope @ wb[h,:64,:]   (batched z=16)
    mma_gemm_kernel<<<dim3(2,32,NHEAD),256,MMA_SMEM>>>(
        ROWS,256,64, q,1536,96, wkv_b,256,128*256, qlat,NHEAD*DLAT,DLAT);

    // 6. C2
    c2_kernel<<<1024,256>>>(fc_c_w, fc_c_b, c2);

    // 7. P2 = kv_norm @ fc_p_w + b
    sgemm_kernel<64,64,16,4,4><<<dim3(1,64,1),256>>>(
        ROWS,64,256, kvnorm,256, fc_p_w,64, p2,64, fc_p_b);

    // 8. kv_t gated combine
    kvt_kernel<<<ROWS,128>>>(c2, p2, kvnorm, klat);

    // 9. tensor-core flash attention
    flash_mma_kernel<<<dim3(T_SEQ/BQ,NHEAD,B_SZ),256,FLASH_SMEM>>>(qlat, klat, x);

    // 10. xv = x @ wbT[h]               (batched z=16)
    mma_gemm_kernel<<<dim3(1,32,NHEAD),256,MMA_SMEM>>>(
        ROWS,64,256, x,NHEAD*256,256, wbT,64,256*64, xv,1024,64);

    // 11. out = xv @ wo                 (4096 x 2048 x 1024)
    mma_gemm_kernel<<<dim3(16,32,1),256,MMA_SMEM>>>(
        ROWS,E_DIM,1024, xv,1024,0, wo,E_DIM,0, out,E_DIM,0);
}